// round 16
// baseline (speedup 1.0000x reference)
#include <cuda_runtime.h>
#include <math.h>
#include <stdint.h>

// Problem constants
#define IDIM   384
#define JDIM   384
#define NTOK   (IDIM*JDIM)      // 147456
#define CDIM   128
#define HEADS  4
#define HDIM   32
#define QSCALE 0.17677669529663687f   // 1/sqrt(32)

// -------- scratch (device globals; no allocation allowed) --------
__device__ float g_xln[(size_t)NTOK*CDIM];   // tf32 bits
__device__ float g_q  [(size_t)NTOK*CDIM];   // tf32 bits (scaled)
__device__ float g_k  [(size_t)NTOK*CDIM];   // tf32 bits
__device__ float g_v  [(size_t)NTOK*CDIM];   // tf32 bits
__device__ float g_gt [(size_t)NTOK*CDIM];   // fp32 sigmoid gate
__device__ float g_og [(size_t)NTOK*CDIM];   // tf32 bits (o * gate)
__device__ float g_tb [(size_t)HEADS*NTOK];  // fp32 [h][q*384+k]
__device__ float g_wt [4*16384];             // tf32 bits wq,wk,wv,wg
__device__ float g_wot[16384];               // tf32 bits wo

// ---------- tf32 mma.sync helpers ----------
__device__ __forceinline__ uint32_t f2tf(float x) {
    uint32_t r;
    asm("cvt.rna.tf32.f32 %0, %1;" : "=r"(r) : "f"(x));
    return r;
}
__device__ __forceinline__ void mma_tf32(float* d,
                                         uint32_t a0, uint32_t a1,
                                         uint32_t a2, uint32_t a3,
                                         uint32_t b0, uint32_t b1) {
    asm volatile(
        "mma.sync.aligned.m16n8k8.row.col.f32.tf32.tf32.f32 "
        "{%0,%1,%2,%3}, {%4,%5,%6,%7}, {%8,%9}, {%0,%1,%2,%3};"
        : "+f"(d[0]), "+f"(d[1]), "+f"(d[2]), "+f"(d[3])
        : "r"(a0), "r"(a1), "r"(a2), "r"(a3), "r"(b0), "r"(b1));
}

// =====================================================================
// Kernel 0: convert weights to tf32 (one-shot, tiny)
// =====================================================================
__global__ __launch_bounds__(256) void wconv_kernel(
    const float* __restrict__ wq, const float* __restrict__ wk,
    const float* __restrict__ wv, const float* __restrict__ wg,
    const float* __restrict__ wo)
{
    int idx = blockIdx.x * 256 + threadIdx.x;   // < 81920
    int w   = idx >> 14;
    int off = idx & 16383;
    const float* src = (w == 0) ? wq : (w == 1) ? wk : (w == 2) ? wv
                     : (w == 3) ? wg : wo;
    float v = src[off];
    float t = __uint_as_float(f2tf(v));
    if (w < 4) g_wt[idx] = t;
    else       g_wot[off] = t;
}

// =====================================================================
// Kernel 1: LayerNorm (tf32 output) + tri-bias projection (fp32)
// =====================================================================
__global__ __launch_bounds__(256) void ln_z_kernel(
    const float* __restrict__ x,
    const float* __restrict__ lnw, const float* __restrict__ lnb,
    const float* __restrict__ wz,  const float* __restrict__ bz)
{
    int warp = threadIdx.x >> 5;
    int lane = threadIdx.x & 31;
    size_t token = (size_t)blockIdx.x * 8 + warp;

    float4 xv = ((const float4*)(x + token * CDIM))[lane];

    float s = xv.x + xv.y + xv.z + xv.w;
#pragma unroll
    for (int m = 16; m; m >>= 1) s += __shfl_xor_sync(0xffffffffu, s, m);
    float mu = s * (1.0f / 128.0f);

    float dx = xv.x - mu, dy = xv.y - mu, dz = xv.z - mu, dw = xv.w - mu;
    float s2 = dx*dx + dy*dy + dz*dz + dw*dw;
#pragma unroll
    for (int m = 16; m; m >>= 1) s2 += __shfl_xor_sync(0xffffffffu, s2, m);
    float rstd = rsqrtf(s2 * (1.0f / 128.0f) + 1e-5f);

    float4 wv = ((const float4*)lnw)[lane];
    float4 bv = ((const float4*)lnb)[lane];
    float4 y;
    y.x = dx * rstd * wv.x + bv.x;
    y.y = dy * rstd * wv.y + bv.y;
    y.z = dz * rstd * wv.z + bv.z;
    y.w = dw * rstd * wv.w + bv.w;

    const float4* wzr = (const float4*)wz;
    int c = lane * 4;
    float4 w0 = wzr[c], w1 = wzr[c+1], w2 = wzr[c+2], w3 = wzr[c+3];
    float4 a;
    a.x = y.x*w0.x + y.y*w1.x + y.z*w2.x + y.w*w3.x;
    a.y = y.x*w0.y + y.y*w1.y + y.z*w2.y + y.w*w3.y;
    a.z = y.x*w0.z + y.y*w1.z + y.z*w2.z + y.w*w3.z;
    a.w = y.x*w0.w + y.y*w1.w + y.z*w2.w + y.w*w3.w;
#pragma unroll
    for (int m = 16; m; m >>= 1) {
        a.x += __shfl_xor_sync(0xffffffffu, a.x, m);
        a.y += __shfl_xor_sync(0xffffffffu, a.y, m);
        a.z += __shfl_xor_sync(0xffffffffu, a.z, m);
        a.w += __shfl_xor_sync(0xffffffffu, a.w, m);
    }
    if (lane == 0) {
        g_tb[0*(size_t)NTOK + token] = a.x + bz[0];
        g_tb[1*(size_t)NTOK + token] = a.y + bz[1];
        g_tb[2*(size_t)NTOK + token] = a.z + bz[2];
        g_tb[3*(size_t)NTOK + token] = a.w + bz[3];
    }

    float4 yt;
    yt.x = __uint_as_float(f2tf(y.x));
    yt.y = __uint_as_float(f2tf(y.y));
    yt.z = __uint_as_float(f2tf(y.z));
    yt.w = __uint_as_float(f2tf(y.w));
    ((float4*)(g_xln + token * CDIM))[lane] = yt;
}

// =====================================================================
// Tensor-core projection kernels (mma.sync tf32)
// 256 threads / 8 warps; warp tile 16 rows x 64 cols
// =====================================================================
#define PJ_LD 136
#define PJ_SMEM_BYTES ((64*PJ_LD + 128*PJ_LD)*4)   // 104448

// per-warp compute: acc[8][4] = 16 rows x 64 cols over K=128
__device__ __forceinline__ void pj_compute16(
    const uint32_t* Au, const uint32_t* Bu,
    int m0, int nb, int gr, int tg, float acc[8][4])
{
#pragma unroll
    for (int t = 0; t < 8; t++)
#pragma unroll
        for (int e = 0; e < 4; e++) acc[t][e] = 0.0f;

#pragma unroll 4
    for (int ks = 0; ks < 16; ks++) {
        int k0 = ks * 8;
        uint32_t a0 = Au[(m0+gr)   * PJ_LD + k0 + tg];
        uint32_t a1 = Au[(m0+gr+8) * PJ_LD + k0 + tg];
        uint32_t a2 = Au[(m0+gr)   * PJ_LD + k0 + tg + 4];
        uint32_t a3 = Au[(m0+gr+8) * PJ_LD + k0 + tg + 4];
#pragma unroll
        for (int t = 0; t < 8; t++) {
            int n0 = nb + t * 8;
            uint32_t b0 = Bu[(k0+tg)   * PJ_LD + n0 + gr];
            uint32_t b1 = Bu[(k0+tg+4) * PJ_LD + n0 + gr];
            mma_tf32(acc[t], a0, a1, a2, a3, b0, b1);
        }
    }
}

__global__ __launch_bounds__(256) void proj4_tc(
    const float* __restrict__ A, const float* __restrict__ bg)
{
    extern __shared__ float sm[];
    float* As = sm;                 // [64][136]
    float* Bs = sm + 64 * PJ_LD;    // [128][136]
    const uint32_t* Au = (const uint32_t*)As;
    const uint32_t* Bu = (const uint32_t*)Bs;

    int tid = threadIdx.x;
    size_t rowbase = (size_t)blockIdx.x * 64;

#pragma unroll
    for (int it = 0; it < 8; it++) {
        int idx = it * 256 + tid;
        int m  = idx >> 5;
        int c4 = (idx & 31) << 2;
        *(float4*)(As + m * PJ_LD + c4) =
            *(const float4*)(A + (rowbase + m) * CDIM + c4);
    }

    int w = tid >> 5, lane = tid & 31;
    int gr = lane >> 2, tg = lane & 3;
    int m0 = (w & 3) * 16;
    int nb = (w >> 2) * 64;

    float* outs[4] = {g_q, g_k, g_v, g_gt};

#pragma unroll 1
    for (int wi = 0; wi < 4; wi++) {
        __syncthreads();
#pragma unroll
        for (int it = 0; it < 16; it++) {
            int idx = it * 256 + tid;
            int k  = idx >> 5;
            int n4 = (idx & 31) << 2;
            *(float4*)(Bs + k * PJ_LD + n4) =
                *(const float4*)(g_wt + wi * 16384 + k * 128 + n4);
        }
        __syncthreads();

        float acc[8][4];
        pj_compute16(Au, Bu, m0, nb, gr, tg, acc);

        float* out = outs[wi];
        size_t r0 = rowbase + m0 + gr;
        size_t r1 = r0 + 8;
#pragma unroll
        for (int t = 0; t < 8; t++) {
            int col = nb + t * 8 + tg * 2;
            float2 v0 = make_float2(acc[t][0], acc[t][1]);
            float2 v1 = make_float2(acc[t][2], acc[t][3]);
            if (wi == 0) {
                v0.x = __uint_as_float(f2tf(v0.x * QSCALE));
                v0.y = __uint_as_float(f2tf(v0.y * QSCALE));
                v1.x = __uint_as_float(f2tf(v1.x * QSCALE));
                v1.y = __uint_as_float(f2tf(v1.y * QSCALE));
            } else if (wi < 3) {
                v0.x = __uint_as_float(f2tf(v0.x));
                v0.y = __uint_as_float(f2tf(v0.y));
                v1.x = __uint_as_float(f2tf(v1.x));
                v1.y = __uint_as_float(f2tf(v1.y));
            } else {
                float2 b = *(const float2*)(bg + col);
                v0.x = 1.0f / (1.0f + __expf(-(v0.x + b.x)));
                v0.y = 1.0f / (1.0f + __expf(-(v0.y + b.y)));
                v1.x = 1.0f / (1.0f + __expf(-(v1.x + b.x)));
                v1.y = 1.0f / (1.0f + __expf(-(v1.y + b.y)));
            }
            *(float2*)(out + r0 * CDIM + col) = v0;
            *(float2*)(out + r1 * CDIM + col) = v1;
        }
    }
}

__global__ __launch_bounds__(256) void gemm_out_tc(
    const float* __restrict__ A, const float* __restrict__ bias,
    float* __restrict__ out)
{
    extern __shared__ float sm[];
    float* As = sm;
    float* Bs = sm + 64 * PJ_LD;
    const uint32_t* Au = (const uint32_t*)As;
    const uint32_t* Bu = (const uint32_t*)Bs;

    int tid = threadIdx.x;
    size_t rowbase = (size_t)blockIdx.x * 64;

#pragma unroll
    for (int it = 0; it < 8; it++) {
        int idx = it * 256 + tid;
        int m  = idx >> 5;
        int c4 = (idx & 31) << 2;
        *(float4*)(As + m * PJ_LD + c4) =
            *(const float4*)(A + (rowbase + m) * CDIM + c4);
    }
#pragma unroll
    for (int it = 0; it < 16; it++) {
        int idx = it * 256 + tid;
        int k  = idx >> 5;
        int n4 = (idx & 31) << 2;
        *(float4*)(Bs + k * PJ_LD + n4) =
            *(const float4*)(g_wot + k * 128 + n4);
    }
    __syncthreads();

    int w = tid >> 5, lane = tid & 31;
    int gr = lane >> 2, tg = lane & 3;
    int m0 = (w & 3) * 16;
    int nb = (w >> 2) * 64;

    float acc[8][4];
    pj_compute16(Au, Bu, m0, nb, gr, tg, acc);

    size_t r0 = rowbase + m0 + gr;
    size_t r1 = r0 + 8;
#pragma unroll
    for (int t = 0; t < 8; t++) {
        int col = nb + t * 8 + tg * 2;
        float2 b = *(const float2*)(bias + col);
        float2 v0 = make_float2(acc[t][0] + b.x, acc[t][1] + b.y);
        float2 v1 = make_float2(acc[t][2] + b.x, acc[t][3] + b.y);
        *(float2*)(out + r0 * CDIM + col) = v0;
        *(float2*)(out + r1 * CDIM + col) = v1;
    }
}

// =====================================================================
// Kernel 3: flash attention, q-tile 128 / k-block 64, warp-local softmax.
//   (unchanged from R15 — verified at 404.5us)
// =====================================================================
#define KBS2  64
#define OFF_KS2  4608
#define OFF_VS2  (OFF_KS2 + KBS2*36)            // 6912
#define OFF_MS2  (OFF_VS2 + KBS2*40)            // 9472
#define AT_SMEM_FLOATS (OFF_MS2 + 384)          // 9856
#define AT_SMEM_BYTES  (AT_SMEM_FLOATS*4)       // 39424

__global__ __launch_bounds__(256, 2) void attn_flash(const float* __restrict__ mask)
{
    extern __shared__ float sm[];
    float* Qs = sm;
    float* Ks = sm + OFF_KS2;
    float* Vs = sm + OFF_VS2;
    float* Ms = sm + OFF_MS2;
    const uint32_t* Qu = (const uint32_t*)Qs;
    const uint32_t* Ku = (const uint32_t*)Ks;
    const uint32_t* Vu = (const uint32_t*)Vs;

    int tid = threadIdx.x;
    int qt  = blockIdx.x;                 // 0..2
    int h   = blockIdx.y;                 // 0..3
    int i   = blockIdx.z;                 // 0..383
    size_t base = (size_t)i * JDIM;
    int col0 = h * HDIM;
    int qbase = qt * 128;

    // ---- mask bias + Q fill (128 rows) ----
    for (int k = tid; k < 384; k += 256)
        Ms[k] = 1e9f * (mask[base + k] - 1.0f);
#pragma unroll
    for (int it = 0; it < 4; it++) {
        int idx = it * 256 + tid;
        int q  = idx >> 3;
        int d4 = (idx & 7) << 2;
        *(float4*)(Qs + q * 36 + d4) =
            *(const float4*)(g_q + (base + qbase + q) * CDIM + col0 + d4);
    }
    __syncthreads();

    int w    = tid >> 5;
    int lane = tid & 31;
    int gr   = lane >> 2;   // 0..7
    int tg   = lane & 3;    // 0..3
    int m0   = w * 16;      // warp's 16-row m-tile
    int r0 = m0 + gr, r1 = r0 + 8;

    // hoist Q fragments
    uint32_t aq[4][4];
#pragma unroll
    for (int ks = 0; ks < 4; ks++) {
        int k0 = ks * 8;
        aq[ks][0] = Qu[r0 * 36 + k0 + tg];
        aq[ks][1] = Qu[r1 * 36 + k0 + tg];
        aq[ks][2] = Qu[r0 * 36 + k0 + tg + 4];
        aq[ks][3] = Qu[r1 * 36 + k0 + tg + 4];
    }

    const float* tb0 = g_tb + (size_t)h * NTOK + (size_t)(qbase + r0) * JDIM;
    const float* tb1 = tb0 + 8 * JDIM;

    float oacc[4][4];
#pragma unroll
    for (int t = 0; t < 4; t++)
#pragma unroll
        for (int e = 0; e < 4; e++) oacc[t][e] = 0.0f;
    float mrun0 = -1e30f, mrun1 = -1e30f;
    float l0 = 0.0f, l1 = 0.0f;

    int srcA = gr * 4 + (tg >> 1);
    int srcB = srcA + 2;
    bool odd = (tg & 1);

#pragma unroll 1
    for (int kb = 0; kb < 6; kb++) {
        __syncthreads();   // WAR: prior block's Ks/Vs reads complete
        // ---- fill Ks[64][36], Vs[64][40] ----
#pragma unroll
        for (int it = 0; it < 2; it++) {
            int idx = it * 256 + tid;
            int k  = idx >> 3;
            int d4 = (idx & 7) << 2;
            size_t grow = (base + kb * KBS2 + k) * CDIM + col0 + d4;
            *(float4*)(Ks + k * 36 + d4) = *(const float4*)(g_k + grow);
            *(float4*)(Vs + k * 40 + d4) = *(const float4*)(g_v + grow);
        }
        __syncthreads();

        // ---- QK^T -> sacc (full 64-wide block for this warp's rows) ----
        float sacc[8][4];
#pragma unroll
        for (int t = 0; t < 8; t++)
#pragma unroll
            for (int e = 0; e < 4; e++) sacc[t][e] = 0.0f;

#pragma unroll
        for (int ks = 0; ks < 4; ks++) {
            int k0 = ks * 8;
#pragma unroll
            for (int t = 0; t < 8; t++) {
                int n = t * 8 + gr;
                uint32_t b0 = Ku[n * 36 + k0 + tg];
                uint32_t b1 = Ku[n * 36 + k0 + tg + 4];
                mma_tf32(sacc[t], aq[ks][0], aq[ks][1], aq[ks][2], aq[ks][3], b0, b1);
            }
        }

        // ---- biases + row max (warp-local: quad reduce = full row) ----
        float mA = -1e30f, mB = -1e30f;
        int kgbase = kb * KBS2;
#pragma unroll
        for (int t = 0; t < 8; t++) {
            int col = kgbase + t * 8 + tg * 2;
            float2 tA = *(const float2*)(tb0 + col);
            float2 tB = *(const float2*)(tb1 + col);
            float2 mm = *(const float2*)(Ms + col);
            sacc[t][0] += tA.x + mm.x;  sacc[t][1] += tA.y + mm.y;
            sacc[t][2] += tB.x + mm.x;  sacc[t][3] += tB.y + mm.y;
            mA = fmaxf(mA, fmaxf(sacc[t][0], sacc[t][1]));
            mB = fmaxf(mB, fmaxf(sacc[t][2], sacc[t][3]));
        }
        mA = fmaxf(mA, __shfl_xor_sync(0xffffffffu, mA, 1));
        mA = fmaxf(mA, __shfl_xor_sync(0xffffffffu, mA, 2));
        mB = fmaxf(mB, __shfl_xor_sync(0xffffffffu, mB, 1));
        mB = fmaxf(mB, __shfl_xor_sync(0xffffffffu, mB, 2));

        // ---- online update (no smem exchange needed) ----
        float mn0 = fmaxf(mrun0, mA);
        float mn1 = fmaxf(mrun1, mB);
        float f0 = __expf(mrun0 - mn0);
        float f1 = __expf(mrun1 - mn1);
        mrun0 = mn0; mrun1 = mn1;

        // ---- exp in registers (tf32 bits into sacc), row sums ----
        float s0 = 0.0f, s1 = 0.0f;
#pragma unroll
        for (int t = 0; t < 8; t++) {
            float e0 = __expf(sacc[t][0] - mn0);
            float e1 = __expf(sacc[t][1] - mn0);
            float e2 = __expf(sacc[t][2] - mn1);
            float e3 = __expf(sacc[t][3] - mn1);
            s0 += e0 + e1;
            s1 += e2 + e3;
            sacc[t][0] = __uint_as_float(f2tf(e0));
            sacc[t][1] = __uint_as_float(f2tf(e1));
            sacc[t][2] = __uint_as_float(f2tf(e2));
            sacc[t][3] = __uint_as_float(f2tf(e3));
        }
        s0 += __shfl_xor_sync(0xffffffffu, s0, 1);
        s0 += __shfl_xor_sync(0xffffffffu, s0, 2);
        s1 += __shfl_xor_sync(0xffffffffu, s1, 1);
        s1 += __shfl_xor_sync(0xffffffffu, s1, 2);

        l0 = l0 * f0 + s0;
        l1 = l1 * f1 + s1;
#pragma unroll
        for (int t = 0; t < 4; t++) {
            oacc[t][0] *= f0;  oacc[t][1] *= f0;
            oacc[t][2] *= f1;  oacc[t][3] *= f1;
        }

        // ---- PV over the full 64-wide block, A-frags via shuffle ----
#pragma unroll
        for (int kk = 0; kk < 8; kk++) {
            float x0 = __shfl_sync(0xffffffffu, sacc[kk][0], srcA);
            float y0 = __shfl_sync(0xffffffffu, sacc[kk][1], srcA);
            float x1 = __shfl_sync(0xffffffffu, sacc[kk][2], srcA);
            float y1 = __shfl_sync(0xffffffffu, sacc[kk][3], srcA);
            float X0 = __shfl_sync(0xffffffffu, sacc[kk][0], srcB);
            float Y0 = __shfl_sync(0xffffffffu, sacc[kk][1], srcB);
            float X1 = __shfl_sync(0xffffffffu, sacc[kk][2], srcB);
            float Y1 = __shfl_sync(0xffffffffu, sacc[kk][3], srcB);
            uint32_t a0 = __float_as_uint(odd ? y0 : x0);
            uint32_t a1 = __float_as_uint(odd ? y1 : x1);
            uint32_t a2 = __float_as_uint(odd ? Y0 : X0);
            uint32_t a3 = __float_as_uint(odd ? Y1 : X1);
            int k0 = kk * 8;
#pragma unroll
            for (int dt = 0; dt < 4; dt++) {
                int n0 = dt * 8;
                uint32_t b0 = Vu[(k0+tg)   * 40 + n0 + gr];
                uint32_t b1 = Vu[(k0+tg+4) * 40 + n0 + gr];
                mma_tf32(oacc[dt], a0, a1, a2, a3, b0, b1);
            }
        }
    }

    // ---- epilogue: direct write (no cross-warp reduction) ----
    {
        float inv0 = 1.0f / l0;
        float inv1 = 1.0f / l1;
        size_t tok0 = base + qbase + r0;
        size_t tok1 = base + qbase + r1;
#pragma unroll
        for (int dt = 0; dt < 4; dt++) {
            int c = dt * 8 + tg * 2;
            int col = col0 + c;
            float2 gA = *(const float2*)(g_gt + tok0 * CDIM + col);
            float2 gB = *(const float2*)(g_gt + tok1 * CDIM + col);
            float2 o0, o1;
            o0.x = __uint_as_float(f2tf(oacc[dt][0] * inv0 * gA.x));
            o0.y = __uint_as_float(f2tf(oacc[dt][1] * inv0 * gA.y));
            o1.x = __uint_as_float(f2tf(oacc[dt][2] * inv1 * gB.x));
            o1.y = __uint_as_float(f2tf(oacc[dt][3] * inv1 * gB.y));
            *(float2*)(g_og + tok0 * CDIM + col) = o0;
            *(float2*)(g_og + tok1 * CDIM + col) = o1;
        }
    }
}

// =====================================================================
// launch
// =====================================================================
extern "C" void kernel_launch(void* const* d_in, const int* in_sizes, int n_in,
                              void* d_out, int out_size)
{
    const float* x    = (const float*)d_in[0];
    const float* mask = (const float*)d_in[1];
    const float* lnw  = (const float*)d_in[2];
    const float* lnb  = (const float*)d_in[3];
    const float* wz   = (const float*)d_in[4];
    const float* bz   = (const float*)d_in[5];
    const float* wq   = (const float*)d_in[6];
    const float* wk   = (const float*)d_in[7];
    const float* wv   = (const float*)d_in[8];
    const float* wg   = (const float*)d_in[9];
    const float* bg   = (const float*)d_in[10];
    const float* wo   = (const float*)d_in[11];
    const float* bo   = (const float*)d_in[12];
    float* out = (float*)d_out;

    float *p_xln, *p_og;
    cudaGetSymbolAddress((void**)&p_xln, g_xln);
    cudaGetSymbolAddress((void**)&p_og,  g_og);

    cudaFuncSetAttribute(proj4_tc, cudaFuncAttributeMaxDynamicSharedMemorySize,
                         PJ_SMEM_BYTES);
    cudaFuncSetAttribute(gemm_out_tc, cudaFuncAttributeMaxDynamicSharedMemorySize,
                         PJ_SMEM_BYTES);
    cudaFuncSetAttribute(attn_flash, cudaFuncAttributeMaxDynamicSharedMemorySize,
                         AT_SMEM_BYTES);

    // 0) weight conversion (tf32)
    wconv_kernel<<<320, 256>>>(wq, wk, wv, wg, wo);

    // 1) LayerNorm + tri-bias
    ln_z_kernel<<<NTOK / 8, 256>>>(x, lnw, lnb, wz, bz);

    // 2) fused projections q/k/v/gate (tensor, 256 thr)
    proj4_tc<<<NTOK / 64, 256, PJ_SMEM_BYTES>>>(p_xln, bg);

    // 3) flash attention (q128/k64, warp-local softmax) — unchanged
    attn_flash<<<dim3(3, HEADS, IDIM), 256, AT_SMEM_BYTES>>>(mask);

    // 4) output projection (tensor, 256 thr)
    gemm_out_tc<<<NTOK / 64, 256, PJ_SMEM_BYTES>>>(p_og, bo, out);
}

// round 17
// speedup vs baseline: 1.0288x; 1.0288x over previous
#include <cuda_runtime.h>
#include <math.h>
#include <stdint.h>

// Problem constants
#define IDIM   384
#define JDIM   384
#define NTOK   (IDIM*JDIM)      // 147456
#define CDIM   128
#define HEADS  4
#define HDIM   32
#define QSCALE 0.17677669529663687f   // 1/sqrt(32)

// -------- scratch (device globals; no allocation allowed) --------
__device__ float g_q  [(size_t)NTOK*CDIM];   // tf32 bits (scaled)
__device__ float g_k  [(size_t)NTOK*CDIM];   // tf32 bits
__device__ float g_v  [(size_t)NTOK*CDIM];   // tf32 bits
__device__ float g_gt [(size_t)NTOK*CDIM];   // fp32 sigmoid gate
__device__ float g_og [(size_t)NTOK*CDIM];   // tf32 bits (o * gate)
__device__ float g_tb [(size_t)HEADS*NTOK];  // fp32 [h][q*384+k]
__device__ float g_wt [4*16384];             // tf32 bits wq,wk,wv,wg
__device__ float g_wot[16384];               // tf32 bits wo

// ---------- tf32 mma.sync helpers ----------
__device__ __forceinline__ uint32_t f2tf(float x) {
    uint32_t r;
    asm("cvt.rna.tf32.f32 %0, %1;" : "=r"(r) : "f"(x));
    return r;
}
__device__ __forceinline__ void mma_tf32(float* d,
                                         uint32_t a0, uint32_t a1,
                                         uint32_t a2, uint32_t a3,
                                         uint32_t b0, uint32_t b1) {
    asm volatile(
        "mma.sync.aligned.m16n8k8.row.col.f32.tf32.tf32.f32 "
        "{%0,%1,%2,%3}, {%4,%5,%6,%7}, {%8,%9}, {%0,%1,%2,%3};"
        : "+f"(d[0]), "+f"(d[1]), "+f"(d[2]), "+f"(d[3])
        : "r"(a0), "r"(a1), "r"(a2), "r"(a3), "r"(b0), "r"(b1));
}

// =====================================================================
// Kernel 0: convert weights to tf32 (one-shot, tiny)
// =====================================================================
__global__ __launch_bounds__(256) void wconv_kernel(
    const float* __restrict__ wq, const float* __restrict__ wk,
    const float* __restrict__ wv, const float* __restrict__ wg,
    const float* __restrict__ wo)
{
    int idx = blockIdx.x * 256 + threadIdx.x;   // < 81920
    int w   = idx >> 14;
    int off = idx & 16383;
    const float* src = (w == 0) ? wq : (w == 1) ? wk : (w == 2) ? wv
                     : (w == 3) ? wg : wo;
    float v = src[off];
    float t = __uint_as_float(f2tf(v));
    if (w < 4) g_wt[idx] = t;
    else       g_wot[off] = t;
}

// =====================================================================
// Projection kernel with FUSED LayerNorm + tri-bias
// 256 threads / 8 warps; warp tile 16 rows x 64 cols
// A-fill = in-kernel LN of x rows (warp-per-token), writes g_tb too.
// =====================================================================
#define PJ_LD 136
#define PJ_SMEM_BYTES ((64*PJ_LD + 128*PJ_LD)*4)   // 104448

__device__ __forceinline__ void pj_compute16(
    const uint32_t* Au, const uint32_t* Bu,
    int m0, int nb, int gr, int tg, float acc[8][4])
{
#pragma unroll
    for (int t = 0; t < 8; t++)
#pragma unroll
        for (int e = 0; e < 4; e++) acc[t][e] = 0.0f;

#pragma unroll 4
    for (int ks = 0; ks < 16; ks++) {
        int k0 = ks * 8;
        uint32_t a0 = Au[(m0+gr)   * PJ_LD + k0 + tg];
        uint32_t a1 = Au[(m0+gr+8) * PJ_LD + k0 + tg];
        uint32_t a2 = Au[(m0+gr)   * PJ_LD + k0 + tg + 4];
        uint32_t a3 = Au[(m0+gr+8) * PJ_LD + k0 + tg + 4];
#pragma unroll
        for (int t = 0; t < 8; t++) {
            int n0 = nb + t * 8;
            uint32_t b0 = Bu[(k0+tg)   * PJ_LD + n0 + gr];
            uint32_t b1 = Bu[(k0+tg+4) * PJ_LD + n0 + gr];
            mma_tf32(acc[t], a0, a1, a2, a3, b0, b1);
        }
    }
}

__global__ __launch_bounds__(256) void proj4_tc(
    const float* __restrict__ x,
    const float* __restrict__ lnw, const float* __restrict__ lnb,
    const float* __restrict__ wz,  const float* __restrict__ bz,
    const float* __restrict__ bg)
{
    extern __shared__ float sm[];
    float* As = sm;                 // [64][136] tf32 bits of LN(x)
    float* Bs = sm + 64 * PJ_LD;    // [128][136]
    const uint32_t* Au = (const uint32_t*)As;
    const uint32_t* Bu = (const uint32_t*)Bs;

    int tid = threadIdx.x;
    size_t rowbase = (size_t)blockIdx.x * 64;

    int w = tid >> 5, lane = tid & 31;

    // ---- fused LayerNorm + tri-bias: warp handles 8 tokens ----
#pragma unroll 1
    for (int it = 0; it < 8; it++) {
        int m = w * 8 + it;
        size_t token = rowbase + m;

        float4 xv = ((const float4*)(x + token * CDIM))[lane];

        float s = xv.x + xv.y + xv.z + xv.w;
#pragma unroll
        for (int mm = 16; mm; mm >>= 1) s += __shfl_xor_sync(0xffffffffu, s, mm);
        float mu = s * (1.0f / 128.0f);

        float dx = xv.x - mu, dy = xv.y - mu, dz = xv.z - mu, dw = xv.w - mu;
        float s2 = dx*dx + dy*dy + dz*dz + dw*dw;
#pragma unroll
        for (int mm = 16; mm; mm >>= 1) s2 += __shfl_xor_sync(0xffffffffu, s2, mm);
        float rstd = rsqrtf(s2 * (1.0f / 128.0f) + 1e-5f);

        float4 wv = ((const float4*)lnw)[lane];
        float4 bv = ((const float4*)lnb)[lane];
        float4 y;
        y.x = dx * rstd * wv.x + bv.x;
        y.y = dy * rstd * wv.y + bv.y;
        y.z = dz * rstd * wv.z + bv.z;
        y.w = dw * rstd * wv.w + bv.w;

        // tri-bias (fp32)
        const float4* wzr = (const float4*)wz;
        int c = lane * 4;
        float4 w0 = wzr[c], w1 = wzr[c+1], w2 = wzr[c+2], w3 = wzr[c+3];
        float4 a;
        a.x = y.x*w0.x + y.y*w1.x + y.z*w2.x + y.w*w3.x;
        a.y = y.x*w0.y + y.y*w1.y + y.z*w2.y + y.w*w3.y;
        a.z = y.x*w0.z + y.y*w1.z + y.z*w2.z + y.w*w3.z;
        a.w = y.x*w0.w + y.y*w1.w + y.z*w2.w + y.w*w3.w;
#pragma unroll
        for (int mm = 16; mm; mm >>= 1) {
            a.x += __shfl_xor_sync(0xffffffffu, a.x, mm);
            a.y += __shfl_xor_sync(0xffffffffu, a.y, mm);
            a.z += __shfl_xor_sync(0xffffffffu, a.z, mm);
            a.w += __shfl_xor_sync(0xffffffffu, a.w, mm);
        }
        if (lane == 0) {
            g_tb[0*(size_t)NTOK + token] = a.x + bz[0];
            g_tb[1*(size_t)NTOK + token] = a.y + bz[1];
            g_tb[2*(size_t)NTOK + token] = a.z + bz[2];
            g_tb[3*(size_t)NTOK + token] = a.w + bz[3];
        }

        float4 yt;
        yt.x = __uint_as_float(f2tf(y.x));
        yt.y = __uint_as_float(f2tf(y.y));
        yt.z = __uint_as_float(f2tf(y.z));
        yt.w = __uint_as_float(f2tf(y.w));
        *(float4*)(As + m * PJ_LD + lane * 4) = yt;
    }

    int gr = lane >> 2, tg = lane & 3;
    int m0 = (w & 3) * 16;
    int nb = (w >> 2) * 64;

    float* outs[4] = {g_q, g_k, g_v, g_gt};

#pragma unroll 1
    for (int wi = 0; wi < 4; wi++) {
        __syncthreads();
#pragma unroll
        for (int it = 0; it < 16; it++) {
            int idx = it * 256 + tid;
            int k  = idx >> 5;
            int n4 = (idx & 31) << 2;
            *(float4*)(Bs + k * PJ_LD + n4) =
                *(const float4*)(g_wt + wi * 16384 + k * 128 + n4);
        }
        __syncthreads();

        float acc[8][4];
        pj_compute16(Au, Bu, m0, nb, gr, tg, acc);

        float* out = outs[wi];
        size_t r0 = rowbase + m0 + gr;
        size_t r1 = r0 + 8;
#pragma unroll
        for (int t = 0; t < 8; t++) {
            int col = nb + t * 8 + tg * 2;
            float2 v0 = make_float2(acc[t][0], acc[t][1]);
            float2 v1 = make_float2(acc[t][2], acc[t][3]);
            if (wi == 0) {
                v0.x = __uint_as_float(f2tf(v0.x * QSCALE));
                v0.y = __uint_as_float(f2tf(v0.y * QSCALE));
                v1.x = __uint_as_float(f2tf(v1.x * QSCALE));
                v1.y = __uint_as_float(f2tf(v1.y * QSCALE));
            } else if (wi < 3) {
                v0.x = __uint_as_float(f2tf(v0.x));
                v0.y = __uint_as_float(f2tf(v0.y));
                v1.x = __uint_as_float(f2tf(v1.x));
                v1.y = __uint_as_float(f2tf(v1.y));
            } else {
                float2 b = *(const float2*)(bg + col);
                v0.x = 1.0f / (1.0f + __expf(-(v0.x + b.x)));
                v0.y = 1.0f / (1.0f + __expf(-(v0.y + b.y)));
                v1.x = 1.0f / (1.0f + __expf(-(v1.x + b.x)));
                v1.y = 1.0f / (1.0f + __expf(-(v1.y + b.y)));
            }
            *(float2*)(out + r0 * CDIM + col) = v0;
            *(float2*)(out + r1 * CDIM + col) = v1;
        }
    }
}

__global__ __launch_bounds__(256) void gemm_out_tc(
    const float* __restrict__ A, const float* __restrict__ bias,
    float* __restrict__ out)
{
    extern __shared__ float sm[];
    float* As = sm;
    float* Bs = sm + 64 * PJ_LD;
    const uint32_t* Au = (const uint32_t*)As;
    const uint32_t* Bu = (const uint32_t*)Bs;

    int tid = threadIdx.x;
    size_t rowbase = (size_t)blockIdx.x * 64;

#pragma unroll
    for (int it = 0; it < 8; it++) {
        int idx = it * 256 + tid;
        int m  = idx >> 5;
        int c4 = (idx & 31) << 2;
        *(float4*)(As + m * PJ_LD + c4) =
            *(const float4*)(A + (rowbase + m) * CDIM + c4);
    }
#pragma unroll
    for (int it = 0; it < 16; it++) {
        int idx = it * 256 + tid;
        int k  = idx >> 5;
        int n4 = (idx & 31) << 2;
        *(float4*)(Bs + k * PJ_LD + n4) =
            *(const float4*)(g_wot + k * 128 + n4);
    }
    __syncthreads();

    int w = tid >> 5, lane = tid & 31;
    int gr = lane >> 2, tg = lane & 3;
    int m0 = (w & 3) * 16;
    int nb = (w >> 2) * 64;

    float acc[8][4];
    pj_compute16(Au, Bu, m0, nb, gr, tg, acc);

    size_t r0 = rowbase + m0 + gr;
    size_t r1 = r0 + 8;
#pragma unroll
    for (int t = 0; t < 8; t++) {
        int col = nb + t * 8 + tg * 2;
        float2 b = *(const float2*)(bias + col);
        float2 v0 = make_float2(acc[t][0] + b.x, acc[t][1] + b.y);
        float2 v1 = make_float2(acc[t][2] + b.x, acc[t][3] + b.y);
        *(float2*)(out + r0 * CDIM + col) = v0;
        *(float2*)(out + r1 * CDIM + col) = v1;
    }
}

// =====================================================================
// Kernel 3: flash attention, q-tile 128 / k-block 64, warp-local softmax.
//   (unchanged — verified at 404.5us)
// =====================================================================
#define KBS2  64
#define OFF_KS2  4608
#define OFF_VS2  (OFF_KS2 + KBS2*36)            // 6912
#define OFF_MS2  (OFF_VS2 + KBS2*40)            // 9472
#define AT_SMEM_FLOATS (OFF_MS2 + 384)          // 9856
#define AT_SMEM_BYTES  (AT_SMEM_FLOATS*4)       // 39424

__global__ __launch_bounds__(256, 2) void attn_flash(const float* __restrict__ mask)
{
    extern __shared__ float sm[];
    float* Qs = sm;
    float* Ks = sm + OFF_KS2;
    float* Vs = sm + OFF_VS2;
    float* Ms = sm + OFF_MS2;
    const uint32_t* Qu = (const uint32_t*)Qs;
    const uint32_t* Ku = (const uint32_t*)Ks;
    const uint32_t* Vu = (const uint32_t*)Vs;

    int tid = threadIdx.x;
    int qt  = blockIdx.x;                 // 0..2
    int h   = blockIdx.y;                 // 0..3
    int i   = blockIdx.z;                 // 0..383
    size_t base = (size_t)i * JDIM;
    int col0 = h * HDIM;
    int qbase = qt * 128;

    // ---- mask bias + Q fill (128 rows) ----
    for (int k = tid; k < 384; k += 256)
        Ms[k] = 1e9f * (mask[base + k] - 1.0f);
#pragma unroll
    for (int it = 0; it < 4; it++) {
        int idx = it * 256 + tid;
        int q  = idx >> 3;
        int d4 = (idx & 7) << 2;
        *(float4*)(Qs + q * 36 + d4) =
            *(const float4*)(g_q + (base + qbase + q) * CDIM + col0 + d4);
    }
    __syncthreads();

    int w    = tid >> 5;
    int lane = tid & 31;
    int gr   = lane >> 2;   // 0..7
    int tg   = lane & 3;    // 0..3
    int m0   = w * 16;      // warp's 16-row m-tile
    int r0 = m0 + gr, r1 = r0 + 8;

    // hoist Q fragments
    uint32_t aq[4][4];
#pragma unroll
    for (int ks = 0; ks < 4; ks++) {
        int k0 = ks * 8;
        aq[ks][0] = Qu[r0 * 36 + k0 + tg];
        aq[ks][1] = Qu[r1 * 36 + k0 + tg];
        aq[ks][2] = Qu[r0 * 36 + k0 + tg + 4];
        aq[ks][3] = Qu[r1 * 36 + k0 + tg + 4];
    }

    const float* tb0 = g_tb + (size_t)h * NTOK + (size_t)(qbase + r0) * JDIM;
    const float* tb1 = tb0 + 8 * JDIM;

    float oacc[4][4];
#pragma unroll
    for (int t = 0; t < 4; t++)
#pragma unroll
        for (int e = 0; e < 4; e++) oacc[t][e] = 0.0f;
    float mrun0 = -1e30f, mrun1 = -1e30f;
    float l0 = 0.0f, l1 = 0.0f;

    int srcA = gr * 4 + (tg >> 1);
    int srcB = srcA + 2;
    bool odd = (tg & 1);

#pragma unroll 1
    for (int kb = 0; kb < 6; kb++) {
        __syncthreads();   // WAR: prior block's Ks/Vs reads complete
        // ---- fill Ks[64][36], Vs[64][40] ----
#pragma unroll
        for (int it = 0; it < 2; it++) {
            int idx = it * 256 + tid;
            int k  = idx >> 3;
            int d4 = (idx & 7) << 2;
            size_t grow = (base + kb * KBS2 + k) * CDIM + col0 + d4;
            *(float4*)(Ks + k * 36 + d4) = *(const float4*)(g_k + grow);
            *(float4*)(Vs + k * 40 + d4) = *(const float4*)(g_v + grow);
        }
        __syncthreads();

        // ---- QK^T -> sacc (full 64-wide block for this warp's rows) ----
        float sacc[8][4];
#pragma unroll
        for (int t = 0; t < 8; t++)
#pragma unroll
            for (int e = 0; e < 4; e++) sacc[t][e] = 0.0f;

#pragma unroll
        for (int ks = 0; ks < 4; ks++) {
            int k0 = ks * 8;
#pragma unroll
            for (int t = 0; t < 8; t++) {
                int n = t * 8 + gr;
                uint32_t b0 = Ku[n * 36 + k0 + tg];
                uint32_t b1 = Ku[n * 36 + k0 + tg + 4];
                mma_tf32(sacc[t], aq[ks][0], aq[ks][1], aq[ks][2], aq[ks][3], b0, b1);
            }
        }

        // ---- biases + row max (warp-local: quad reduce = full row) ----
        float mA = -1e30f, mB = -1e30f;
        int kgbase = kb * KBS2;
#pragma unroll
        for (int t = 0; t < 8; t++) {
            int col = kgbase + t * 8 + tg * 2;
            float2 tA = *(const float2*)(tb0 + col);
            float2 tB = *(const float2*)(tb1 + col);
            float2 mm = *(const float2*)(Ms + col);
            sacc[t][0] += tA.x + mm.x;  sacc[t][1] += tA.y + mm.y;
            sacc[t][2] += tB.x + mm.x;  sacc[t][3] += tB.y + mm.y;
            mA = fmaxf(mA, fmaxf(sacc[t][0], sacc[t][1]));
            mB = fmaxf(mB, fmaxf(sacc[t][2], sacc[t][3]));
        }
        mA = fmaxf(mA, __shfl_xor_sync(0xffffffffu, mA, 1));
        mA = fmaxf(mA, __shfl_xor_sync(0xffffffffu, mA, 2));
        mB = fmaxf(mB, __shfl_xor_sync(0xffffffffu, mB, 1));
        mB = fmaxf(mB, __shfl_xor_sync(0xffffffffu, mB, 2));

        // ---- online update (no smem exchange needed) ----
        float mn0 = fmaxf(mrun0, mA);
        float mn1 = fmaxf(mrun1, mB);
        float f0 = __expf(mrun0 - mn0);
        float f1 = __expf(mrun1 - mn1);
        mrun0 = mn0; mrun1 = mn1;

        // ---- exp in registers (tf32 bits into sacc), row sums ----
        float s0 = 0.0f, s1 = 0.0f;
#pragma unroll
        for (int t = 0; t < 8; t++) {
            float e0 = __expf(sacc[t][0] - mn0);
            float e1 = __expf(sacc[t][1] - mn0);
            float e2 = __expf(sacc[t][2] - mn1);
            float e3 = __expf(sacc[t][3] - mn1);
            s0 += e0 + e1;
            s1 += e2 + e3;
            sacc[t][0] = __uint_as_float(f2tf(e0));
            sacc[t][1] = __uint_as_float(f2tf(e1));
            sacc[t][2] = __uint_as_float(f2tf(e2));
            sacc[t][3] = __uint_as_float(f2tf(e3));
        }
        s0 += __shfl_xor_sync(0xffffffffu, s0, 1);
        s0 += __shfl_xor_sync(0xffffffffu, s0, 2);
        s1 += __shfl_xor_sync(0xffffffffu, s1, 1);
        s1 += __shfl_xor_sync(0xffffffffu, s1, 2);

        l0 = l0 * f0 + s0;
        l1 = l1 * f1 + s1;
#pragma unroll
        for (int t = 0; t < 4; t++) {
            oacc[t][0] *= f0;  oacc[t][1] *= f0;
            oacc[t][2] *= f1;  oacc[t][3] *= f1;
        }

        // ---- PV over the full 64-wide block, A-frags via shuffle ----
#pragma unroll
        for (int kk = 0; kk < 8; kk++) {
            float x0 = __shfl_sync(0xffffffffu, sacc[kk][0], srcA);
            float y0 = __shfl_sync(0xffffffffu, sacc[kk][1], srcA);
            float x1 = __shfl_sync(0xffffffffu, sacc[kk][2], srcA);
            float y1 = __shfl_sync(0xffffffffu, sacc[kk][3], srcA);
            float X0 = __shfl_sync(0xffffffffu, sacc[kk][0], srcB);
            float Y0 = __shfl_sync(0xffffffffu, sacc[kk][1], srcB);
            float X1 = __shfl_sync(0xffffffffu, sacc[kk][2], srcB);
            float Y1 = __shfl_sync(0xffffffffu, sacc[kk][3], srcB);
            uint32_t a0 = __float_as_uint(odd ? y0 : x0);
            uint32_t a1 = __float_as_uint(odd ? y1 : x1);
            uint32_t a2 = __float_as_uint(odd ? Y0 : X0);
            uint32_t a3 = __float_as_uint(odd ? Y1 : X1);
            int k0 = kk * 8;
#pragma unroll
            for (int dt = 0; dt < 4; dt++) {
                int n0 = dt * 8;
                uint32_t b0 = Vu[(k0+tg)   * 40 + n0 + gr];
                uint32_t b1 = Vu[(k0+tg+4) * 40 + n0 + gr];
                mma_tf32(oacc[dt], a0, a1, a2, a3, b0, b1);
            }
        }
    }

    // ---- epilogue: direct write (no cross-warp reduction) ----
    {
        float inv0 = 1.0f / l0;
        float inv1 = 1.0f / l1;
        size_t tok0 = base + qbase + r0;
        size_t tok1 = base + qbase + r1;
#pragma unroll
        for (int dt = 0; dt < 4; dt++) {
            int c = dt * 8 + tg * 2;
            int col = col0 + c;
            float2 gA = *(const float2*)(g_gt + tok0 * CDIM + col);
            float2 gB = *(const float2*)(g_gt + tok1 * CDIM + col);
            float2 o0, o1;
            o0.x = __uint_as_float(f2tf(oacc[dt][0] * inv0 * gA.x));
            o0.y = __uint_as_float(f2tf(oacc[dt][1] * inv0 * gA.y));
            o1.x = __uint_as_float(f2tf(oacc[dt][2] * inv1 * gB.x));
            o1.y = __uint_as_float(f2tf(oacc[dt][3] * inv1 * gB.y));
            *(float2*)(g_og + tok0 * CDIM + col) = o0;
            *(float2*)(g_og + tok1 * CDIM + col) = o1;
        }
    }
}

// =====================================================================
// launch
// =====================================================================
extern "C" void kernel_launch(void* const* d_in, const int* in_sizes, int n_in,
                              void* d_out, int out_size)
{
    const float* x    = (const float*)d_in[0];
    const float* mask = (const float*)d_in[1];
    const float* lnw  = (const float*)d_in[2];
    const float* lnb  = (const float*)d_in[3];
    const float* wz   = (const float*)d_in[4];
    const float* bz   = (const float*)d_in[5];
    const float* wq   = (const float*)d_in[6];
    const float* wk   = (const float*)d_in[7];
    const float* wv   = (const float*)d_in[8];
    const float* wg   = (const float*)d_in[9];
    const float* bg   = (const float*)d_in[10];
    const float* wo   = (const float*)d_in[11];
    const float* bo   = (const float*)d_in[12];
    float* out = (float*)d_out;

    float *p_og;
    cudaGetSymbolAddress((void**)&p_og, g_og);

    cudaFuncSetAttribute(proj4_tc, cudaFuncAttributeMaxDynamicSharedMemorySize,
                         PJ_SMEM_BYTES);
    cudaFuncSetAttribute(gemm_out_tc, cudaFuncAttributeMaxDynamicSharedMemorySize,
                         PJ_SMEM_BYTES);
    cudaFuncSetAttribute(attn_flash, cudaFuncAttributeMaxDynamicSharedMemorySize,
                         AT_SMEM_BYTES);

    // 0) weight conversion (tf32)
    wconv_kernel<<<320, 256>>>(wq, wk, wv, wg, wo);

    // 1+2) fused LayerNorm + tri-bias + projections q/k/v/gate
    proj4_tc<<<NTOK / 64, 256, PJ_SMEM_BYTES>>>(x, lnw, lnb, wz, bz, bg);

    // 3) flash attention (q128/k64, warp-local softmax) — unchanged
    attn_flash<<<dim3(3, HEADS, IDIM), 256, AT_SMEM_BYTES>>>(mask);

    // 4) output projection (tensor)
    gemm_out_tc<<<NTOK / 64, 256, PJ_SMEM_BYTES>>>(p_og, bo, out);
}